// round 7
// baseline (speedup 1.0000x reference)
#include <cuda_runtime.h>
#include <cuda_fp16.h>
#include <mma.h>

using namespace nvcuda;

#define Bsz  4096
#define Nseq 512
#define Csz  512
#define PHId 128
#define H1d  512
#define H2d  256

// Scratch (__device__ globals; no allocations allowed)
__device__ __half g_hist [Bsz * Csz];    // 4 MB   per-row label histogram (fp16, exact)
__device__ __half g_Wc   [Csz * H1d];    // 512 KB Wc = Wphi @ W1 (fp16)
__device__ __half g_W2   [H1d * H2d];    // 256 KB
__device__ float  g_b1eff[H1d];          // b1 + 512 * (b_phi @ W1), exact fp32

// ---------------------------------------------------------------------------
// cp.async helpers (LDGSTS, 16B)
// ---------------------------------------------------------------------------
__device__ __forceinline__ void cp_async16(void* smem, const void* gmem) {
    unsigned s = (unsigned)__cvta_generic_to_shared(smem);
    asm volatile("cp.async.cg.shared.global [%0], [%1], 16;\n" :: "r"(s), "l"(gmem));
}
__device__ __forceinline__ void cp_commit() {
    asm volatile("cp.async.commit_group;\n");
}
template <int NN>
__device__ __forceinline__ void cp_wait() {
    asm volatile("cp.async.wait_group %0;\n" :: "n"(NN));
}

// ---------------------------------------------------------------------------
// Prep kernel, block ranges:
//   [0,512)   : per-row histograms (8 rows/block, smem atomics) -> g_hist fp16
//   [512,640) : Wc = Wphi @ W1  (fp32 compute, fp16 store), 32x64 tile/block
//   [640,672) : W2 fp32 -> fp16 convert
//   672       : b1_eff = b1 + 512*(b_phi @ W1) in fp32
// ---------------------------------------------------------------------------
__global__ void __launch_bounds__(256) prep_kernel(const int* __restrict__ x,
                                                   const float* __restrict__ Wphi,
                                                   const float* __restrict__ W1,
                                                   const float* __restrict__ W2,
                                                   const float* __restrict__ bphi,
                                                   const float* __restrict__ b1)
{
    __shared__ __align__(16) char praw[24576];   // 24 KB, aliased per branch
    const int tid = threadIdx.x;

    if (blockIdx.x < 512) {
        int* hs = reinterpret_cast<int*>(praw);  // [8][512]
#pragma unroll
        for (int i = 0; i < 16; i++) hs[tid + i * 256] = 0;
        __syncthreads();

        const int warp = tid >> 5, lane = tid & 31;
        const int row = blockIdx.x * 8 + warp;
        const int* xr = x + (size_t)row * Nseq;
#pragma unroll 4
        for (int j = lane; j < Nseq; j += 32) atomicAdd(&hs[warp * Csz + xr[j]], 1);
        __syncthreads();

#pragma unroll
        for (int e = tid; e < 8 * Csz; e += 256) {
            const int r = e >> 9, c = e & (Csz - 1);
            g_hist[(size_t)(blockIdx.x * 8 + r) * Csz + c] =
                __float2half((float)hs[r * Csz + c]);
        }
    } else if (blockIdx.x < 640) {
        // Wc tile: 32x64 outputs, K = 128 in 2 chunks of 64
        const int cb = blockIdx.x - 512;               // 0..127: 16 x 8 tiles
        const int tr = (cb >> 3) * 32, tcc = (cb & 7) * 64;
        float* sA = reinterpret_cast<float*>(praw);           // [32][64]
        float* sB = reinterpret_cast<float*>(praw + 8192);    // [64][64]
        const int ty = tid >> 4, tx = tid & 15;  // thread -> 2 rows x 4 cols

        float acc[2][4] = {{0.f,0.f,0.f,0.f},{0.f,0.f,0.f,0.f}};

        for (int kc = 0; kc < 2; kc++) {
#pragma unroll
            for (int i = 0; i < 8; i++) {
                const int idx = i * 256 + tid, r = idx >> 6, c = idx & 63;
                sA[r * 64 + c] = Wphi[(size_t)(tr + r) * PHId + kc * 64 + c];
            }
#pragma unroll
            for (int i = 0; i < 16; i++) {
                const int idx = i * 256 + tid, r = idx >> 6, c = idx & 63;
                sB[r * 64 + c] = W1[(size_t)(kc * 64 + r) * H1d + tcc + c];
            }
            __syncthreads();
#pragma unroll 4
            for (int k = 0; k < 64; k++) {
                const float a0 = sA[(ty * 2) * 64 + k];
                const float a1 = sA[(ty * 2 + 1) * 64 + k];
#pragma unroll
                for (int j = 0; j < 4; j++) {
                    const float b = sB[k * 64 + tx * 4 + j];
                    acc[0][j] = fmaf(a0, b, acc[0][j]);
                    acc[1][j] = fmaf(a1, b, acc[1][j]);
                }
            }
            __syncthreads();
        }
#pragma unroll
        for (int i = 0; i < 2; i++)
#pragma unroll
            for (int j = 0; j < 4; j++)
                g_Wc[(size_t)(tr + ty * 2 + i) * H1d + tcc + tx * 4 + j] =
                    __float2half(acc[i][j]);
    } else if (blockIdx.x < 672) {
        const int cb = blockIdx.x - 640;               // 0..31
        const int t = cb * 256 + tid;
        for (int i = t; i < H1d * H2d; i += 32 * 256) g_W2[i] = __float2half(W2[i]);
    } else {
#pragma unroll
        for (int o = tid; o < H1d; o += 256) {
            float s = 0.f;
            for (int k = 0; k < PHId; k++) s = fmaf(bphi[k], W1[k * H1d + o], s);
            g_b1eff[o] = b1[o] + (float)Nseq * s;
        }
    }
}

// ---------------------------------------------------------------------------
// Mega kernel: per block of 32 batch rows, fully fused
//   h1 = relu(hist @ Wc + b1eff)   (h1 lives only in smem, per 64-col tile)
//   acc2 += h1_tile @ W2[K-chunk]  (register-resident across all chunks)
//   out = relu(acc2 + b2) @ W3 + b3
// 256 threads = 8 warps (2 row x 4 col groups of 16). Unified 96-tile
// cp.async double-buffered B stream: per ct1, 8 Wc tiles then 4 W2 tiles.
// ---------------------------------------------------------------------------
#define OFF_HIST 0            // 32 x 536 half   = 34304 B
#define OFF_H1T  34304        // 32 x 72  half   =  4608 B
#define OFF_BS   38912        // 2 x 64 x 72 half= 18432 B
#define OFF_CS   57344        // 32 x 68 float   =  8704 B
#define OFF_B1   66048        // 512 float
#define OFF_B2   68096        // 256 float
#define OFF_W3   69120        // 256 float
#define SMEM_MEGA 70144

__global__ void __launch_bounds__(256) mega_kernel(const float* __restrict__ b2,
                                                   const float* __restrict__ W3,
                                                   const float* __restrict__ b3,
                                                   float* __restrict__ out)
{
    extern __shared__ __align__(16) char dyn[];
    __half* histS = reinterpret_cast<__half*>(dyn + OFF_HIST);  // ldm 536
    __half* h1T   = reinterpret_cast<__half*>(dyn + OFF_H1T);   // ldm 72
    __half* BsB   = reinterpret_cast<__half*>(dyn + OFF_BS);    // 2 x [64][72]
    float*  CsS   = reinterpret_cast<float*>(dyn + OFF_CS);     // ldm 68
    float*  b1S   = reinterpret_cast<float*>(dyn + OFF_B1);
    float*  b2S   = reinterpret_cast<float*>(dyn + OFF_B2);
    float*  w3S   = reinterpret_cast<float*>(dyn + OFF_W3);

    const int tid  = threadIdx.x;
    const int warp = tid >> 5;
    const int wrow = warp & 1;      // 16-row group
    const int wcol = warp >> 1;     // 16-col group (of 64-col tile)
    const int rowBase = blockIdx.x * 32;

    // initial loads: hist rows + biases (group 0)
    {
        const __half* hsrc = g_hist + (size_t)rowBase * Csz;
#pragma unroll
        for (int i = 0; i < 8; i++) {
            const int idx = i * 256 + tid, r = idx >> 6, c = (idx & 63) << 3;
            cp_async16(histS + r * 536 + c, hsrc + r * 512 + c);
        }
        if (tid < 128)      cp_async16(b1S + tid * 4,         g_b1eff + tid * 4);
        else if (tid < 192) cp_async16(b2S + (tid - 128) * 4, b2 + (tid - 128) * 4);
        else                cp_async16(w3S + (tid - 192) * 4, W3 + (tid - 192) * 4);
        cp_commit();
    }

    // unified B-tile loader: t in [0,96): ct1 = t/12; phase<8 -> Wc, else W2
    const int lr = tid >> 3, lc = (tid & 7) << 3;
    auto load_tile = [&](int s, int t) {
        const int ct1 = t / 12, ph = t - ct1 * 12;
        const __half* src;
        int stride;
        if (ph < 8) { src = g_Wc + (size_t)(ph * 64) * H1d + ct1 * 64;       stride = H1d; }
        else        { src = g_W2 + (size_t)(ct1 * 64) * H2d + (ph - 8) * 64; stride = H2d; }
        __half* d = BsB + s * (64 * 72);
        cp_async16(d + lr * 72 + lc,        src + (size_t)lr * stride + lc);
        cp_async16(d + (lr + 32) * 72 + lc, src + (size_t)(lr + 32) * stride + lc);
    };

    wmma::fragment<wmma::accumulator, 16, 16, 16, float> acc1, acc2[4];
#pragma unroll
    for (int j = 0; j < 4; j++) wmma::fill_fragment(acc2[j], 0.f);

    load_tile(0, 0); cp_commit();

    for (int t = 0; t < 96; t++) {
        cp_wait<0>();
        __syncthreads();
        if (t + 1 < 96) load_tile((t + 1) & 1, t + 1);
        cp_commit();

        const int ct1 = t / 12, ph = t - ct1 * 12;
        const __half* bs = BsB + (t & 1) * (64 * 72);

        if (ph < 8) {
            // GEMM1: acc1 += hist[:, ph*64..] @ Wc-tile
            if (ph == 0) wmma::fill_fragment(acc1, 0.f);
#pragma unroll
            for (int kk = 0; kk < 4; kk++) {
                wmma::fragment<wmma::matrix_a, 16, 16, 16, __half, wmma::row_major> af;
                wmma::fragment<wmma::matrix_b, 16, 16, 16, __half, wmma::row_major> bf;
                wmma::load_matrix_sync(af, histS + (wrow * 16) * 536 + ph * 64 + kk * 16, 536);
                wmma::load_matrix_sync(bf, bs + (kk * 16) * 72 + wcol * 16, 72);
                wmma::mma_sync(acc1, af, bf, acc1);
            }
            if (ph == 7) {
                // epilogue1: h1 tile = relu(acc + b1eff slice), fp16 into h1T
                wmma::store_matrix_sync(CsS + (wrow * 16) * 68 + wcol * 16, acc1, 68,
                                        wmma::mem_row_major);
                __syncthreads();
                const int r = tid >> 3, c0 = (tid & 7) << 3;
                __half h8[8];
#pragma unroll
                for (int q = 0; q < 8; q++)
                    h8[q] = __float2half(
                        fmaxf(CsS[r * 68 + c0 + q] + b1S[ct1 * 64 + c0 + q], 0.f));
                *reinterpret_cast<int4*>(h1T + r * 72 + c0) = *reinterpret_cast<int4*>(h8);
                __syncthreads();
            }
        } else {
            // GEMM2 partial: acc2[ct2] += h1T @ W2-tile (K-chunk ct1)
            const int ct2 = ph - 8;
#pragma unroll
            for (int kk = 0; kk < 4; kk++) {
                wmma::fragment<wmma::matrix_a, 16, 16, 16, __half, wmma::row_major> af;
                wmma::fragment<wmma::matrix_b, 16, 16, 16, __half, wmma::row_major> bf;
                wmma::load_matrix_sync(af, h1T + (wrow * 16) * 72 + kk * 16, 72);
                wmma::load_matrix_sync(bf, bs + (kk * 16) * 72 + wcol * 16, 72);
                wmma::mma_sync(acc2[ct2], af, bf, acc2[ct2]);
            }
        }
    }

    // final epilogue: out = relu(acc2 + b2) @ W3 + b3, fixed order (deterministic)
    float rowSum = 0.f;
#pragma unroll
    for (int ct2 = 0; ct2 < 4; ct2++) {
        __syncthreads();
        wmma::store_matrix_sync(CsS + (wrow * 16) * 68 + wcol * 16, acc2[ct2], 68,
                                wmma::mem_row_major);
        __syncthreads();
        if (tid < 32) {
#pragma unroll 8
            for (int c = 0; c < 64; c++) {
                const float h = fmaxf(CsS[tid * 68 + c] + b2S[ct2 * 64 + c], 0.f);
                rowSum = fmaf(h, w3S[ct2 * 64 + c], rowSum);
            }
        }
    }
    if (tid < 32) out[rowBase + tid] = rowSum + b3[0];
}

// ---------------------------------------------------------------------------
extern "C" void kernel_launch(void* const* d_in, const int* in_sizes, int n_in,
                              void* d_out, int out_size)
{
    const int*   x    = (const int*)  d_in[0];
    const float* Wphi = (const float*)d_in[1];
    const float* bphi = (const float*)d_in[2];
    const float* W1   = (const float*)d_in[3];
    const float* b1   = (const float*)d_in[4];
    const float* W2   = (const float*)d_in[5];
    const float* b2   = (const float*)d_in[6];
    const float* W3   = (const float*)d_in[7];
    const float* b3   = (const float*)d_in[8];
    float* out = (float*)d_out;

    cudaFuncSetAttribute(mega_kernel, cudaFuncAttributeMaxDynamicSharedMemorySize,
                         SMEM_MEGA);

    // 0: histograms + Wc = Wphi@W1 + W2 convert + b1_eff
    prep_kernel<<<673, 256>>>(x, Wphi, W1, W2, bphi, b1);

    // 1: fully fused MLP: 128 blocks x 32 rows
    mega_kernel<<<Bsz / 32, 256, SMEM_MEGA>>>(b2, W3, b3, out);
}

// round 8
// speedup vs baseline: 2.0809x; 2.0809x over previous
#include <cuda_runtime.h>
#include <cuda_fp16.h>
#include <mma.h>

using namespace nvcuda;

#define Bsz  4096
#define Nseq 512
#define Csz  512
#define PHId 128
#define H1d  512
#define H2d  256

// Scratch (__device__ globals; no allocations allowed)
__device__ __half g_hist [Bsz * Csz];    // 4 MB   per-row label histogram (fp16, exact)
__device__ __half g_h1   [Bsz * H1d];    // 4 MB
__device__ float  g_part [4 * Bsz];      // partial dots (deterministic reduce)
__device__ __half g_Wc   [Csz * H1d];    // 512 KB  Wc = Wphi @ W1 (fp16)
__device__ __half g_W2   [H1d * H2d];
__device__ float  g_b1eff[H1d];          // b1 + 512 * (b_phi @ W1), exact fp32
__device__ int    g_cnt  [Bsz / 64];     // per row-block completion counters

// ---------------------------------------------------------------------------
// cp.async helpers (LDGSTS, 16B)
// ---------------------------------------------------------------------------
__device__ __forceinline__ void cp_async16(void* smem, const void* gmem) {
    unsigned s = (unsigned)__cvta_generic_to_shared(smem);
    asm volatile("cp.async.cg.shared.global [%0], [%1], 16;\n" :: "r"(s), "l"(gmem));
}
__device__ __forceinline__ void cp_commit() {
    asm volatile("cp.async.commit_group;\n");
}
template <int NN>
__device__ __forceinline__ void cp_wait() {
    asm volatile("cp.async.wait_group %0;\n" :: "n"(NN));
}

// ---------------------------------------------------------------------------
// Prep kernel, block ranges:
//   [0,512)   : per-row histograms (8 rows/block, smem atomics) -> g_hist fp16
//   [512,576) : Wc = Wphi @ W1  (fp32 compute, fp16 store), 64x64 tile/block
//   [576,608) : W2 fp32 -> fp16 convert
//   608       : b1_eff = b1 + 512*(b_phi @ W1) fp32; reset g_cnt
// ---------------------------------------------------------------------------
__global__ void __launch_bounds__(256) prep_kernel(const int* __restrict__ x,
                                                   const float* __restrict__ Wphi,
                                                   const float* __restrict__ W1,
                                                   const float* __restrict__ W2,
                                                   const float* __restrict__ bphi,
                                                   const float* __restrict__ b1)
{
    __shared__ __align__(16) char praw[16384];   // 16 KB, aliased per branch
    const int tid = threadIdx.x;

    if (blockIdx.x < 512) {
        int* hs = reinterpret_cast<int*>(praw);  // [8][512]
#pragma unroll
        for (int i = 0; i < 16; i++) hs[tid + i * 256] = 0;
        __syncthreads();

        const int warp = tid >> 5, lane = tid & 31;
        const int row = blockIdx.x * 8 + warp;
        const int* xr = x + (size_t)row * Nseq;
#pragma unroll 4
        for (int j = lane; j < Nseq; j += 32) atomicAdd(&hs[warp * Csz + xr[j]], 1);
        __syncthreads();

#pragma unroll
        for (int e = tid; e < 8 * Csz; e += 256) {
            const int r = e >> 9, c = e & (Csz - 1);
            g_hist[(size_t)(blockIdx.x * 8 + r) * Csz + c] =
                __float2half((float)hs[r * Csz + c]);
        }
    } else if (blockIdx.x < 576) {
        // Wc tile: 64x64 outputs, K = 128 in 4 chunks of 32
        const int cb = blockIdx.x - 512;           // 0..63 -> 8x8 tiles
        const int tr = (cb >> 3) * 64, tcc = (cb & 7) * 64;
        float* sA = reinterpret_cast<float*>(praw);         // [64][32]
        float* sB = reinterpret_cast<float*>(praw + 8192);  // [32][64]
        const int ty = tid >> 4, tx = tid & 15;    // thread -> 4x4 outputs

        float acc[4][4];
#pragma unroll
        for (int i = 0; i < 4; i++)
#pragma unroll
            for (int j = 0; j < 4; j++) acc[i][j] = 0.f;

        for (int kc = 0; kc < 4; kc++) {
#pragma unroll
            for (int q = 0; q < 8; q++) {
                const int e = tid * 8 + q;         // A: 64x32
                sA[e] = Wphi[(size_t)(tr + (e >> 5)) * PHId + kc * 32 + (e & 31)];
            }
#pragma unroll
            for (int q = 0; q < 8; q++) {
                const int e = tid * 8 + q;         // B: 32x64
                sB[e] = W1[(size_t)(kc * 32 + (e >> 6)) * H1d + tcc + (e & 63)];
            }
            __syncthreads();
#pragma unroll
            for (int k = 0; k < 32; k++) {
                float a[4], b[4];
#pragma unroll
                for (int i = 0; i < 4; i++) a[i] = sA[(ty * 4 + i) * 32 + k];
#pragma unroll
                for (int j = 0; j < 4; j++) b[j] = sB[k * 64 + tx * 4 + j];
#pragma unroll
                for (int i = 0; i < 4; i++)
#pragma unroll
                    for (int j = 0; j < 4; j++) acc[i][j] = fmaf(a[i], b[j], acc[i][j]);
            }
            __syncthreads();
        }
#pragma unroll
        for (int i = 0; i < 4; i++)
#pragma unroll
            for (int j = 0; j < 4; j++)
                g_Wc[(size_t)(tr + ty * 4 + i) * H1d + tcc + tx * 4 + j] =
                    __float2half(acc[i][j]);
    } else if (blockIdx.x < 608) {
        const int cb = blockIdx.x - 576;           // 0..31
        const int t = cb * 256 + tid;
        for (int i = t; i < H1d * H2d; i += 32 * 256) g_W2[i] = __float2half(W2[i]);
    } else {
#pragma unroll
        for (int o = tid; o < H1d; o += 256) {
            float s = 0.f;
            for (int k = 0; k < PHId; k++) s = fmaf(bphi[k], W1[k * H1d + o], s);
            g_b1eff[o] = b1[o] + (float)Nseq * s;
        }
        if (tid < Bsz / 64) g_cnt[tid] = 0;        // reset last-block counters
    }
}

// ---------------------------------------------------------------------------
// Pipelined fp16 tensor-core GEMM, fp32 accumulate, fused bias+ReLU epilogue.
// BM=64, BN=64, BK=64; 128 threads = 4 warps (2x2), warp tile 32x32
// (2 A-frags x 2 B-frags, fragment reuse). 2-stage cp.async pipeline,
// ONE __syncthreads per k-iteration (wait-before-sync pattern).
// FUSED: epilogue computes relu(acc+bias) dot W3-slice -> g_part, then the
// last col-block per row-block sums the 4 partials in fixed order -> out.
// ---------------------------------------------------------------------------
template <bool FUSED>
__global__ void __launch_bounds__(128) gemm_tc(const __half* __restrict__ A,
                                               const __half* __restrict__ B,
                                               const float* __restrict__ bias,
                                               const float* __restrict__ W3,
                                               const float* __restrict__ b3,
                                               __half* __restrict__ C,
                                               float* __restrict__ out,
                                               int M, int N, int K)
{
    constexpr int BM = 64, BN = 64, BK = 64, T = 128;
    __shared__ __align__(16) union USM {
        struct { __half A[2][BM][BK + 8]; __half B[2][BK][BN + 8]; } in;   // 36 KB
        float Cs[BM][BN + 4];
    } sm;
    __shared__ float w3s[BN];
    __shared__ float bs[BN];
    __shared__ float sp[BM][2];
    __shared__ int isLast;

    const int tid  = threadIdx.x;
    const int warp = tid >> 5;
    const int wr   = warp & 1;      // row group: 32 rows
    const int wc   = warp >> 1;     // col group: 32 cols
    const int rowBase = blockIdx.y * BM;
    const int colBase = blockIdx.x * BN;

    if (FUSED && tid < BN) {
        w3s[tid] = W3[colBase + tid];
        bs[tid]  = bias[colBase + tid];
    }

    // loader map: 64 rows x 8 chunks(16B) = 512 chunks, 4 per thread
    const int lr = tid >> 3, lc = (tid & 7) << 3;

    auto load_tile = [&](int s, int kt) {
        const __half* Ak = A + (size_t)rowBase * K + kt * BK;
#pragma unroll
        for (int r = 0; r < 4; r++)
            cp_async16(&sm.in.A[s][lr + 16 * r][lc], Ak + (size_t)(lr + 16 * r) * K + lc);
        const __half* Bk = B + (size_t)(kt * BK) * N + colBase;
#pragma unroll
        for (int r = 0; r < 4; r++)
            cp_async16(&sm.in.B[s][lr + 16 * r][lc], Bk + (size_t)(lr + 16 * r) * N + lc);
    };

    wmma::fragment<wmma::accumulator, 16, 16, 16, float> acc[2][2];
#pragma unroll
    for (int i = 0; i < 2; i++)
#pragma unroll
        for (int j = 0; j < 2; j++) wmma::fill_fragment(acc[i][j], 0.f);

    const int KT = K / BK;
    load_tile(0, 0); cp_commit();

    for (int kt = 0; kt < KT; kt++) {
        cp_wait<0>();
        __syncthreads();             // all data of stage kt&1 visible; prev readers done
        if (kt + 1 < KT) load_tile((kt + 1) & 1, kt + 1);
        cp_commit();

        const int s = kt & 1;
#pragma unroll
        for (int kk = 0; kk < 4; kk++) {
            wmma::fragment<wmma::matrix_a, 16, 16, 16, __half, wmma::row_major> af[2];
            wmma::fragment<wmma::matrix_b, 16, 16, 16, __half, wmma::row_major> bf[2];
#pragma unroll
            for (int i = 0; i < 2; i++)
                wmma::load_matrix_sync(af[i], &sm.in.A[s][wr * 32 + i * 16][kk * 16], BK + 8);
#pragma unroll
            for (int j = 0; j < 2; j++)
                wmma::load_matrix_sync(bf[j], &sm.in.B[s][kk * 16][wc * 32 + j * 16], BN + 8);
#pragma unroll
            for (int i = 0; i < 2; i++)
#pragma unroll
                for (int j = 0; j < 2; j++)
                    wmma::mma_sync(acc[i][j], af[i], bf[j], acc[i][j]);
        }
    }
    __syncthreads();                 // before union re-use as Cs

    // spill accumulators to smem
#pragma unroll
    for (int i = 0; i < 2; i++)
#pragma unroll
        for (int j = 0; j < 2; j++)
            wmma::store_matrix_sync(&sm.Cs[wr * 32 + i * 16][wc * 32 + j * 16],
                                    acc[i][j], BN + 4, wmma::mem_row_major);
    __syncthreads();

    if (!FUSED) {
        // bias + relu + fp16 store, 8 cols/thread (STG.128), 4 iterations
#pragma unroll
        for (int e = tid; e < BM * (BN / 8); e += T) {
            const int r = e >> 3, c = (e & 7) << 3;
            __half h8[8];
#pragma unroll
            for (int q = 0; q < 8; q++) {
                float v = fmaxf(sm.Cs[r][c + q] + bias[colBase + c + q], 0.f);
                h8[q] = __float2half(v);
            }
            *reinterpret_cast<int4*>(&C[(size_t)(rowBase + r) * N + colBase + c]) =
                *reinterpret_cast<int4*>(h8);
        }
    } else {
        // thread -> (row, 32-col segment): 64 rows x 2 segs = 128 threads
        const int r = tid >> 1, sc = (tid & 1) << 5;
        float v = 0.f;
#pragma unroll
        for (int i = 0; i < 32; i++) {
            const float h = fmaxf(sm.Cs[r][sc + i] + bs[sc + i], 0.f);
            v = fmaf(h, w3s[sc + i], v);
        }
        sp[r][tid & 1] = v;
        __syncthreads();
        if (tid < BM)
            g_part[(size_t)blockIdx.x * M + rowBase + tid] = sp[tid][0] + sp[tid][1];

        // last-block-done deterministic reduce (fixed summation order)
        __threadfence();
        __syncthreads();
        if (tid == 0) {
            const int old = atomicAdd(&g_cnt[blockIdx.y], 1);
            isLast = (old == 3);
        }
        __syncthreads();
        if (isLast) {
            __threadfence();
            if (tid < BM) {
                const int row = rowBase + tid;
                const float* P = g_part;
                float s = (__ldcg(&P[row]) + __ldcg(&P[M + row]))
                        + (__ldcg(&P[2 * M + row]) + __ldcg(&P[3 * M + row]));
                out[row] = s + b3[0];
            }
        }
    }
}

// ---------------------------------------------------------------------------
extern "C" void kernel_launch(void* const* d_in, const int* in_sizes, int n_in,
                              void* d_out, int out_size)
{
    const int*   x    = (const int*)  d_in[0];
    const float* Wphi = (const float*)d_in[1];
    const float* bphi = (const float*)d_in[2];
    const float* W1   = (const float*)d_in[3];
    const float* b1   = (const float*)d_in[4];
    const float* W2   = (const float*)d_in[5];
    const float* b2   = (const float*)d_in[6];
    const float* W3   = (const float*)d_in[7];
    const float* b3   = (const float*)d_in[8];
    float* out = (float*)d_out;

    __half *hist_p, *h1_p, *Wc_p, *W2_p;
    float *b1eff_p;
    cudaGetSymbolAddress((void**)&hist_p,  g_hist);
    cudaGetSymbolAddress((void**)&h1_p,    g_h1);
    cudaGetSymbolAddress((void**)&Wc_p,    g_Wc);
    cudaGetSymbolAddress((void**)&W2_p,    g_W2);
    cudaGetSymbolAddress((void**)&b1eff_p, g_b1eff);

    // 0: histograms + Wc = Wphi@W1 + W2 convert + b1_eff + counter reset
    prep_kernel<<<609, 256>>>(x, Wphi, W1, W2, bphi, b1);

    // 1: h1 = relu(hist @ Wc + b1_eff)   (4096x512)@(512x512) -> 512 blocks
    {
        dim3 grid(H1d / 64, Bsz / 64);
        gemm_tc<false><<<grid, 128>>>(hist_p, Wc_p, b1eff_p, nullptr, nullptr,
                                      h1_p, nullptr, Bsz, H1d, Csz);
    }
    // 2: fused h2 = relu(h1 @ W2 + b2); out = h2 @ W3 + b3 (last-block reduce)
    {
        dim3 grid(H2d / 64, Bsz / 64);
        gemm_tc<true><<<grid, 128>>>(h1_p, W2_p, b2, W3, b3,
                                     nullptr, out, Bsz, H2d, H1d);
    }
}

// round 9
// speedup vs baseline: 2.1624x; 1.0392x over previous
#include <cuda_runtime.h>
#include <cuda_fp16.h>
#include <mma.h>

using namespace nvcuda;

#define Bsz  4096
#define Nseq 512
#define Csz  512
#define PHId 128
#define H1d  512
#define H2d  256

// Scratch (__device__ globals; no allocations allowed)
__device__ __half g_hist [Bsz * Csz];    // 4 MB   per-row label histogram (fp16, exact)
__device__ __half g_h1   [Bsz * H1d];    // 4 MB
__device__ float  g_part [4 * Bsz];      // partial dots (deterministic reduce)
__device__ __half g_Wc   [Csz * H1d];    // 512 KB  Wc = Wphi @ W1 (fp16)
__device__ __half g_W2   [H1d * H2d];
__device__ float  g_b1eff[H1d];          // b1 + 512 * (b_phi @ W1), exact fp32

// ---------------------------------------------------------------------------
// cp.async helpers (LDGSTS, 16B)
// ---------------------------------------------------------------------------
__device__ __forceinline__ void cp_async16(void* smem, const void* gmem) {
    unsigned s = (unsigned)__cvta_generic_to_shared(smem);
    asm volatile("cp.async.cg.shared.global [%0], [%1], 16;\n" :: "r"(s), "l"(gmem));
}
__device__ __forceinline__ void cp_commit() {
    asm volatile("cp.async.commit_group;\n");
}
template <int NN>
__device__ __forceinline__ void cp_wait() {
    asm volatile("cp.async.wait_group %0;\n" :: "n"(NN));
}

// ---------------------------------------------------------------------------
// Prep kernel, block ranges:
//   [0,512)   : per-row histograms (8 rows/block, smem atomics) -> g_hist fp16
//   [512,576) : Wc = Wphi @ W1 via wmma HMMA (fp16 in, fp32 acc), 64x64/block
//   [576,608) : W2 fp32 -> fp16 convert
//   608       : b1_eff = b1 + 512*(b_phi @ W1) in fp32
// ---------------------------------------------------------------------------
__global__ void __launch_bounds__(256) prep_kernel(const int* __restrict__ x,
                                                   const float* __restrict__ Wphi,
                                                   const float* __restrict__ W1,
                                                   const float* __restrict__ W2,
                                                   const float* __restrict__ bphi,
                                                   const float* __restrict__ b1)
{
    __shared__ __align__(16) char praw[35840];   // 35 KB, aliased per branch
    const int tid = threadIdx.x;

    if (blockIdx.x < 512) {
        int* hs = reinterpret_cast<int*>(praw);  // [8][512]
#pragma unroll
        for (int i = 0; i < 16; i++) hs[tid + i * 256] = 0;
        __syncthreads();

        const int warp = tid >> 5, lane = tid & 31;
        const int row = blockIdx.x * 8 + warp;
        const int4* xr = reinterpret_cast<const int4*>(x + (size_t)row * Nseq);
        int* hw = hs + warp * Csz;
#pragma unroll
        for (int i = 0; i < 4; i++) {            // 128 int4 per row
            const int4 v = xr[lane + i * 32];
            atomicAdd(&hw[v.x], 1);
            atomicAdd(&hw[v.y], 1);
            atomicAdd(&hw[v.z], 1);
            atomicAdd(&hw[v.w], 1);
        }
        __syncthreads();

#pragma unroll
        for (int e = tid; e < 8 * Csz; e += 256) {
            const int r = e >> 9, c = e & (Csz - 1);
            g_hist[(size_t)(blockIdx.x * 8 + r) * Csz + c] =
                __float2half((float)hs[r * Csz + c]);
        }
    } else if (blockIdx.x < 576) {
        // Wc tile 64x64, K=128, tensor cores. smem: A[64][136]h, B[128][72]h
        const int cb = blockIdx.x - 512;               // 0..63 -> 8x8 tiles
        const int tr = (cb >> 3) * 64, tcc = (cb & 7) * 64;
        __half* sA = reinterpret_cast<__half*>(praw);           // ld 136
        __half* sB = reinterpret_cast<__half*>(praw + 17408);   // ld 72
        float*  sC = reinterpret_cast<float*>(praw);            // ld 68 (aliases sA)

        // A: Wphi[tr..tr+64)[0..128) fp32 -> half. 2048 float4, 8 per thread.
#pragma unroll
        for (int i = 0; i < 8; i++) {
            const int idx = i * 256 + tid;
            const int r = idx >> 5, c4 = (idx & 31) << 2;
            const float4 v = *reinterpret_cast<const float4*>(
                &Wphi[(size_t)(tr + r) * PHId + c4]);
            __half h4[4] = {__float2half(v.x), __float2half(v.y),
                            __float2half(v.z), __float2half(v.w)};
            *reinterpret_cast<uint2*>(&sA[r * 136 + c4]) = *reinterpret_cast<uint2*>(h4);
        }
        // B: W1[0..128)[tcc..tcc+64) fp32 -> half. 2048 float4, 8 per thread.
#pragma unroll
        for (int i = 0; i < 8; i++) {
            const int idx = i * 256 + tid;
            const int r = idx >> 4, c4 = (idx & 15) << 2;
            const float4 v = *reinterpret_cast<const float4*>(
                &W1[(size_t)r * H1d + tcc + c4]);
            __half h4[4] = {__float2half(v.x), __float2half(v.y),
                            __float2half(v.z), __float2half(v.w)};
            *reinterpret_cast<uint2*>(&sB[r * 72 + c4]) = *reinterpret_cast<uint2*>(h4);
        }
        __syncthreads();

        // 8 warps: 2 row-groups x 4 col-groups; warp tile 32x16
        const int wrp = tid >> 5, wr2 = wrp & 1, wc2 = wrp >> 1;
        wmma::fragment<wmma::accumulator, 16, 16, 16, float> ac[2];
        wmma::fill_fragment(ac[0], 0.f);
        wmma::fill_fragment(ac[1], 0.f);
#pragma unroll
        for (int k = 0; k < 8; k++) {
            wmma::fragment<wmma::matrix_a, 16, 16, 16, __half, wmma::row_major> af[2];
            wmma::fragment<wmma::matrix_b, 16, 16, 16, __half, wmma::row_major> bf;
            wmma::load_matrix_sync(af[0], &sA[(wr2 * 32) * 136 + k * 16], 136);
            wmma::load_matrix_sync(af[1], &sA[(wr2 * 32 + 16) * 136 + k * 16], 136);
            wmma::load_matrix_sync(bf, &sB[(k * 16) * 72 + wc2 * 16], 72);
            wmma::mma_sync(ac[0], af[0], bf, ac[0]);
            wmma::mma_sync(ac[1], af[1], bf, ac[1]);
        }
        __syncthreads();       // done reading sA before aliasing as sC
        wmma::store_matrix_sync(&sC[(wr2 * 32) * 68 + wc2 * 16], ac[0], 68,
                                wmma::mem_row_major);
        wmma::store_matrix_sync(&sC[(wr2 * 32 + 16) * 68 + wc2 * 16], ac[1], 68,
                                wmma::mem_row_major);
        __syncthreads();

#pragma unroll
        for (int e = tid; e < 64 * 64; e += 256) {
            const int r = e >> 6, c = e & 63;
            g_Wc[(size_t)(tr + r) * H1d + tcc + c] = __float2half(sC[r * 68 + c]);
        }
    } else if (blockIdx.x < 608) {
        const int cb = blockIdx.x - 576;           // 0..31
        const int t = cb * 256 + tid;
        for (int i = t; i < H1d * H2d; i += 32 * 256) g_W2[i] = __float2half(W2[i]);
    } else {
#pragma unroll
        for (int o = tid; o < H1d; o += 256) {
            float s = 0.f;
            for (int k = 0; k < PHId; k++) s = fmaf(bphi[k], W1[k * H1d + o], s);
            g_b1eff[o] = b1[o] + (float)Nseq * s;
        }
    }
}

// ---------------------------------------------------------------------------
// Pipelined fp16 tensor-core GEMM, fp32 accumulate, fused bias+ReLU epilogue.
// BM=64, BN=64, BK=64; 128 threads = 4 warps (2x2), warp tile 32x32
// (2 A-frags x 2 B-frags, fragment reuse). 2-stage cp.async pipeline,
// ONE __syncthreads per k-iteration (wait-before-sync pattern).
// FUSED: epilogue computes relu(acc+bias) dot W3-slice -> g_part.
// ---------------------------------------------------------------------------
template <bool FUSED>
__global__ void __launch_bounds__(128) gemm_tc(const __half* __restrict__ A,
                                               const __half* __restrict__ B,
                                               const float* __restrict__ bias,
                                               const float* __restrict__ W3,
                                               __half* __restrict__ C,
                                               int M, int N, int K)
{
    constexpr int BM = 64, BN = 64, BK = 64, T = 128;
    __shared__ __align__(16) union USM {
        struct { __half A[2][BM][BK + 8]; __half B[2][BK][BN + 8]; } in;   // 36 KB
        float Cs[BM][BN + 4];
    } sm;
    __shared__ float w3s[BN];
    __shared__ float bs[BN];
    __shared__ float sp[BM][2];

    const int tid  = threadIdx.x;
    const int warp = tid >> 5;
    const int wr   = warp & 1;      // row group: 32 rows
    const int wc   = warp >> 1;     // col group: 32 cols
    const int rowBase = blockIdx.y * BM;
    const int colBase = blockIdx.x * BN;

    if (FUSED && tid < BN) {
        w3s[tid] = W3[colBase + tid];
        bs[tid]  = bias[colBase + tid];
    }

    // loader map: 64 rows x 8 chunks(16B) = 512 chunks, 4 per thread
    const int lr = tid >> 3, lc = (tid & 7) << 3;

    auto load_tile = [&](int s, int kt) {
        const __half* Ak = A + (size_t)rowBase * K + kt * BK;
#pragma unroll
        for (int r = 0; r < 4; r++)
            cp_async16(&sm.in.A[s][lr + 16 * r][lc], Ak + (size_t)(lr + 16 * r) * K + lc);
        const __half* Bk = B + (size_t)(kt * BK) * N + colBase;
#pragma unroll
        for (int r = 0; r < 4; r++)
            cp_async16(&sm.in.B[s][lr + 16 * r][lc], Bk + (size_t)(lr + 16 * r) * N + lc);
    };

    wmma::fragment<wmma::accumulator, 16, 16, 16, float> acc[2][2];
#pragma unroll
    for (int i = 0; i < 2; i++)
#pragma unroll
        for (int j = 0; j < 2; j++) wmma::fill_fragment(acc[i][j], 0.f);

    const int KT = K / BK;
    load_tile(0, 0); cp_commit();

    for (int kt = 0; kt < KT; kt++) {
        cp_wait<0>();
        __syncthreads();             // all data of stage kt&1 visible; prev readers done
        if (kt + 1 < KT) load_tile((kt + 1) & 1, kt + 1);
        cp_commit();

        const int s = kt & 1;
#pragma unroll
        for (int kk = 0; kk < 4; kk++) {
            wmma::fragment<wmma::matrix_a, 16, 16, 16, __half, wmma::row_major> af[2];
            wmma::fragment<wmma::matrix_b, 16, 16, 16, __half, wmma::row_major> bf[2];
#pragma unroll
            for (int i = 0; i < 2; i++)
                wmma::load_matrix_sync(af[i], &sm.in.A[s][wr * 32 + i * 16][kk * 16], BK + 8);
#pragma unroll
            for (int j = 0; j < 2; j++)
                wmma::load_matrix_sync(bf[j], &sm.in.B[s][kk * 16][wc * 32 + j * 16], BN + 8);
#pragma unroll
            for (int i = 0; i < 2; i++)
#pragma unroll
                for (int j = 0; j < 2; j++)
                    wmma::mma_sync(acc[i][j], af[i], bf[j], acc[i][j]);
        }
    }
    __syncthreads();                 // before union re-use as Cs

    // spill accumulators to smem
#pragma unroll
    for (int i = 0; i < 2; i++)
#pragma unroll
        for (int j = 0; j < 2; j++)
            wmma::store_matrix_sync(&sm.Cs[wr * 32 + i * 16][wc * 32 + j * 16],
                                    acc[i][j], BN + 4, wmma::mem_row_major);
    __syncthreads();

    if (!FUSED) {
        // bias + relu + fp16 store, 8 cols/thread (STG.128), 4 iterations
#pragma unroll
        for (int e = tid; e < BM * (BN / 8); e += T) {
            const int r = e >> 3, c = (e & 7) << 3;
            __half h8[8];
#pragma unroll
            for (int q = 0; q < 8; q++) {
                float v = fmaxf(sm.Cs[r][c + q] + bias[colBase + c + q], 0.f);
                h8[q] = __float2half(v);
            }
            *reinterpret_cast<int4*>(&C[(size_t)(rowBase + r) * N + colBase + c]) =
                *reinterpret_cast<int4*>(h8);
        }
    } else {
        // thread -> (row, 32-col segment): 64 rows x 2 segs = 128 threads
        const int r = tid >> 1, sc = (tid & 1) << 5;
        float v = 0.f;
#pragma unroll
        for (int i = 0; i < 32; i++) {
            const float h = fmaxf(sm.Cs[r][sc + i] + bs[sc + i], 0.f);
            v = fmaf(h, w3s[sc + i], v);
        }
        sp[r][tid & 1] = v;
        __syncthreads();
        if (tid < BM)
            g_part[(size_t)blockIdx.x * M + rowBase + tid] = sp[tid][0] + sp[tid][1];
    }
}

// ---------------------------------------------------------------------------
// Deterministic final reduce: out[i] = sum of 4 partials + b3.
// ---------------------------------------------------------------------------
__global__ void __launch_bounds__(256) reduce_kernel(const float* __restrict__ b3,
                                                     float* __restrict__ out)
{
    const int i = blockIdx.x * 256 + threadIdx.x;
    out[i] = ((g_part[i] + g_part[Bsz + i]) + (g_part[2 * Bsz + i] + g_part[3 * Bsz + i]))
             + b3[0];
}

// ---------------------------------------------------------------------------
extern "C" void kernel_launch(void* const* d_in, const int* in_sizes, int n_in,
                              void* d_out, int out_size)
{
    const int*   x    = (const int*)  d_in[0];
    const float* Wphi = (const float*)d_in[1];
    const float* bphi = (const float*)d_in[2];
    const float* W1   = (const float*)d_in[3];
    const float* b1   = (const float*)d_in[4];
    const float* W2   = (const float*)d_in[5];
    const float* b2   = (const float*)d_in[6];
    const float* W3   = (const float*)d_in[7];
    const float* b3   = (const float*)d_in[8];
    float* out = (float*)d_out;

    __half *hist_p, *h1_p, *Wc_p, *W2_p;
    float *b1eff_p;
    cudaGetSymbolAddress((void**)&hist_p,  g_hist);
    cudaGetSymbolAddress((void**)&h1_p,    g_h1);
    cudaGetSymbolAddress((void**)&Wc_p,    g_Wc);
    cudaGetSymbolAddress((void**)&W2_p,    g_W2);
    cudaGetSymbolAddress((void**)&b1eff_p, g_b1eff);

    // 0: histograms + Wc = Wphi@W1 (HMMA) + W2 convert + b1_eff
    prep_kernel<<<609, 256>>>(x, Wphi, W1, W2, bphi, b1);

    // 1: h1 = relu(hist @ Wc + b1_eff)   (4096x512)@(512x512) -> 512 blocks
    {
        dim3 grid(H1d / 64, Bsz / 64);
        gemm_tc<false><<<grid, 128>>>(hist_p, Wc_p, b1eff_p, nullptr,
                                      h1_p, Bsz, H1d, Csz);
    }
    // 2: fused h2 = relu(h1 @ W2 + b2); partials = h2 @ W3 -> 256 blocks
    {
        dim3 grid(H2d / 64, Bsz / 64);
        gemm_tc<true><<<grid, 128>>>(h1_p, W2_p, b2, W3,
                                     nullptr, Bsz, H2d, H1d);
    }
    // 3: deterministic reduce + b3
    reduce_kernel<<<Bsz / 256, 256>>>(b3, out);
}